// round 3
// baseline (speedup 1.0000x reference)
#include <cuda_runtime.h>
#include <cuda_bf16.h>
#include <math.h>
#include <stdint.h>

// Problem constants: B=4, T=2048, C=768, H=12, D=64
#define Bv 4
#define Tv 2048
#define Cv 768
#define Hv 12
#define Dv 64
#define C3v (3 * Cv)     // 2304
#define Mv (Bv * Tv)     // 8192

// ---------------- device scratch (no allocation allowed) -------------------
__device__ float g_qkv[(size_t)Mv * C3v];                      // [B*T, 3C] fp32
__device__ __nv_bfloat16 g_x_hi[(size_t)Mv * Cv];
__device__ __nv_bfloat16 g_x_lo[(size_t)Mv * Cv];
__device__ __nv_bfloat16 g_wA_hi[(size_t)C3v * Cv];            // transposed [3C, C]
__device__ __nv_bfloat16 g_wA_lo[(size_t)C3v * Cv];
__device__ __nv_bfloat16 g_wP_hi[(size_t)Cv * Cv];             // transposed [C, C]
__device__ __nv_bfloat16 g_wP_lo[(size_t)Cv * Cv];
__device__ __nv_bfloat16 g_y_hi[(size_t)Mv * Cv];
__device__ __nv_bfloat16 g_y_lo[(size_t)Mv * Cv];

// ---------------------------------------------------------------------------
// mma.sync m16n8k16 bf16 (baseline PTX — works on plain sm_103 target)
// ---------------------------------------------------------------------------
__device__ __forceinline__ void mma16816(float* c, const uint32_t* a,
                                         uint32_t b0, uint32_t b1) {
    asm volatile(
        "mma.sync.aligned.m16n8k16.row.col.f32.bf16.bf16.f32 "
        "{%0,%1,%2,%3}, {%4,%5,%6,%7}, {%8,%9}, {%0,%1,%2,%3};"
        : "+f"(c[0]), "+f"(c[1]), "+f"(c[2]), "+f"(c[3])
        : "r"(a[0]), "r"(a[1]), "r"(a[2]), "r"(a[3]), "r"(b0), "r"(b1));
}

// ---------------------------------------------------------------------------
// split fp32 -> (hi, lo) bf16, elementwise
// ---------------------------------------------------------------------------
__global__ void split_kernel(const float* __restrict__ in,
                             __nv_bfloat16* __restrict__ hi,
                             __nv_bfloat16* __restrict__ lo, int n) {
    int i = (blockIdx.x * 256 + threadIdx.x) * 4;
    if (i >= n) return;
    float4 v = *(const float4*)(in + i);
    float f[4] = {v.x, v.y, v.z, v.w};
    __nv_bfloat162 h01, h23, l01, l23;
    __nv_bfloat16 h;
    h = __float2bfloat16(f[0]); h01.x = h; l01.x = __float2bfloat16(f[0] - __bfloat162float(h));
    h = __float2bfloat16(f[1]); h01.y = h; l01.y = __float2bfloat16(f[1] - __bfloat162float(h));
    h = __float2bfloat16(f[2]); h23.x = h; l23.x = __float2bfloat16(f[2] - __bfloat162float(h));
    h = __float2bfloat16(f[3]); h23.y = h; l23.y = __float2bfloat16(f[3] - __bfloat162float(h));
    *(__nv_bfloat162*)(hi + i)     = h01;
    *(__nv_bfloat162*)(hi + i + 2) = h23;
    *(__nv_bfloat162*)(lo + i)     = l01;
    *(__nv_bfloat162*)(lo + i + 2) = l23;
}

// ---------------------------------------------------------------------------
// transpose + split: w[K,N] fp32 -> wT[N,K] (hi, lo) bf16
// ---------------------------------------------------------------------------
__global__ void transpose_split(const float* __restrict__ w,
                                __nv_bfloat16* __restrict__ thi,
                                __nv_bfloat16* __restrict__ tlo, int K, int N) {
    __shared__ float st[32][33];
    const int n0 = blockIdx.x * 32, k0 = blockIdx.y * 32;
    const int tx = threadIdx.x, ty = threadIdx.y;          // (32, 8)
    #pragma unroll
    for (int i = 0; i < 4; i++)
        st[ty + 8 * i][tx] = w[(size_t)(k0 + ty + 8 * i) * N + n0 + tx];
    __syncthreads();
    #pragma unroll
    for (int i = 0; i < 4; i++) {
        float f = st[tx][ty + 8 * i];
        __nv_bfloat16 hh = __float2bfloat16(f);
        __nv_bfloat16 ll = __float2bfloat16(f - __bfloat162float(hh));
        size_t o = (size_t)(n0 + ty + 8 * i) * K + k0 + tx;
        thi[o] = hh;
        tlo[o] = ll;
    }
}

// ---------------------------------------------------------------------------
// Tensor-core (mma.sync) bf16-split GEMM:
//   C[M,N] = (Ahi+Alo)[M,K] @ (Bhi+Blo)[N,K]^T + bias
// 3 passes: hi*hi + hi*lo + lo*hi. 128x128 block tile, BK=32, 8 warps (4Mx2N),
// warp tile 32x64. Padded smem (row stride 40 bf16) -> conflict-free frags.
// ---------------------------------------------------------------------------
#define GRS 40   // smem row stride in bf16 (32 + 8 pad)

__global__ __launch_bounds__(256)
void gemm_mma(const __nv_bfloat16* __restrict__ Ahi, const __nv_bfloat16* __restrict__ Alo,
              const __nv_bfloat16* __restrict__ Bhi, const __nv_bfloat16* __restrict__ Blo,
              const float* __restrict__ bias, float* __restrict__ Cmat,
              int N, int K) {
    __shared__ __nv_bfloat16 As[2][128][GRS];   // [hi/lo][row][k]
    __shared__ __nv_bfloat16 Bs[2][128][GRS];   // [hi/lo][n][k]

    const int tid = threadIdx.x;
    const int wid = tid >> 5, lane = tid & 31;
    const int g = lane >> 2, tig = lane & 3;    // mma octet row / quad
    const int bx = blockIdx.x, by = blockIdx.y;
    const int wm = (wid & 3) * 32;              // warp M offset
    const int wn = (wid >> 2) * 64;             // warp N offset

    const int lrow = tid >> 2;                  // 0..63 (global-load row)
    const int lc8  = (tid & 3) * 8;             // 0,8,16,24 (k offset, 8 bf16)

    float acc[2][8][4];
    #pragma unroll
    for (int mt = 0; mt < 2; mt++)
        #pragma unroll
        for (int nt = 0; nt < 8; nt++)
            #pragma unroll
            for (int j = 0; j < 4; j++) acc[mt][nt][j] = 0.f;

    const int nCh = K >> 5;                     // BK = 32
    for (int c = 0; c < nCh; c++) {
        const int k0 = c << 5;
        // load 4 tiles: A hi/lo (rows by*128..), B hi/lo (rows bx*128..)
        #pragma unroll
        for (int i = 0; i < 2; i++) {
            const int r = lrow + i * 64;
            const size_t ga = (size_t)(by * 128 + r) * K + k0 + lc8;
            const size_t gb = (size_t)(bx * 128 + r) * K + k0 + lc8;
            *(uint4*)&As[0][r][lc8] = *(const uint4*)(Ahi + ga);
            *(uint4*)&As[1][r][lc8] = *(const uint4*)(Alo + ga);
            *(uint4*)&Bs[0][r][lc8] = *(const uint4*)(Bhi + gb);
            *(uint4*)&Bs[1][r][lc8] = *(const uint4*)(Blo + gb);
        }
        __syncthreads();

        #pragma unroll
        for (int pass = 0; pass < 3; pass++) {
            const int pa = (pass == 2) ? 1 : 0;  // A: hi,hi,lo
            const int pb = (pass == 1) ? 1 : 0;  // B: hi,lo,hi
            #pragma unroll
            for (int ks = 0; ks < 2; ks++) {
                const int kc = ks * 16 + tig * 2;
                uint32_t afr[2][4];
                #pragma unroll
                for (int mt = 0; mt < 2; mt++) {
                    const int r0 = wm + mt * 16 + g;
                    afr[mt][0] = *(const uint32_t*)&As[pa][r0][kc];
                    afr[mt][1] = *(const uint32_t*)&As[pa][r0 + 8][kc];
                    afr[mt][2] = *(const uint32_t*)&As[pa][r0][kc + 8];
                    afr[mt][3] = *(const uint32_t*)&As[pa][r0 + 8][kc + 8];
                }
                #pragma unroll
                for (int nt = 0; nt < 8; nt++) {
                    const int n0 = wn + nt * 8 + g;
                    const uint32_t b0 = *(const uint32_t*)&Bs[pb][n0][kc];
                    const uint32_t b1 = *(const uint32_t*)&Bs[pb][n0][kc + 8];
                    mma16816(acc[0][nt], afr[0], b0, b1);
                    mma16816(acc[1][nt], afr[1], b0, b1);
                }
            }
        }
        __syncthreads();
    }

    // epilogue: write fp32 + bias
    #pragma unroll
    for (int mt = 0; mt < 2; mt++) {
        #pragma unroll
        for (int nt = 0; nt < 8; nt++) {
            const int rg = by * 128 + wm + mt * 16 + g;
            const int cg = bx * 128 + wn + nt * 8 + tig * 2;
            const float bs0 = __ldg(bias + cg), bs1 = __ldg(bias + cg + 1);
            float2 v0, v1;
            v0.x = acc[mt][nt][0] + bs0;
            v0.y = acc[mt][nt][1] + bs1;
            v1.x = acc[mt][nt][2] + bs0;
            v1.y = acc[mt][nt][3] + bs1;
            *(float2*)(Cmat + (size_t)rg * N + cg)       = v0;
            *(float2*)(Cmat + (size_t)(rg + 8) * N + cg) = v1;
        }
    }
}

// ---------------------------------------------------------------------------
// Causal flash attention (fp32, online softmax). Emits y as bf16 (hi, lo).
// ---------------------------------------------------------------------------
__global__ __launch_bounds__(128)
void attn_kernel(const float* __restrict__ qkv,
                 __nv_bfloat16* __restrict__ yhi, __nv_bfloat16* __restrict__ ylo) {
    constexpr int BQ = 128, BKV = 64;
    const int qt = blockIdx.x;
    const int h  = blockIdx.y;
    const int b  = blockIdx.z;
    const int tid = threadIdx.x;
    const int r = qt * BQ + tid;

    const float* base = qkv + (size_t)b * Tv * C3v;

    __shared__ float Ks[BKV][Dv];
    __shared__ float Vs[BKV][Dv];

    float q[Dv], acc[Dv];
    const float* qrow = base + (size_t)r * C3v + h * Dv;
    const float sc = 0.125f;
    #pragma unroll
    for (int d = 0; d < Dv; d += 4) {
        float4 v = *(const float4*)(qrow + d);
        q[d] = v.x * sc; q[d + 1] = v.y * sc; q[d + 2] = v.z * sc; q[d + 3] = v.w * sc;
    }
    #pragma unroll
    for (int d = 0; d < Dv; d++) acc[d] = 0.f;

    float m = -INFINITY, l = 0.f;
    const int kmax = qt * BQ + BQ;
    for (int kb = 0; kb < kmax; kb += BKV) {
        for (int idx = tid; idx < BKV * (Dv / 4); idx += BQ) {
            const int j = idx / (Dv / 4);
            const int d4 = (idx % (Dv / 4)) * 4;
            const float* krow = base + (size_t)(kb + j) * C3v + h * Dv;
            *(float4*)&Ks[j][d4] = *(const float4*)(krow + Cv + d4);
            *(float4*)&Vs[j][d4] = *(const float4*)(krow + 2 * Cv + d4);
        }
        __syncthreads();

        if (kb <= r) {
            #pragma unroll 1
            for (int j0 = 0; j0 < BKV; j0 += 16) {
                if (kb + j0 > r) break;
                float s[16];
                float cmax = -INFINITY;
                #pragma unroll
                for (int jj = 0; jj < 16; jj++) {
                    const int j = j0 + jj;
                    float dot = 0.f;
                    #pragma unroll
                    for (int d = 0; d < Dv; d += 4) {
                        float4 kv = *(const float4*)&Ks[j][d];
                        dot = fmaf(q[d], kv.x, dot);
                        dot = fmaf(q[d + 1], kv.y, dot);
                        dot = fmaf(q[d + 2], kv.z, dot);
                        dot = fmaf(q[d + 3], kv.w, dot);
                    }
                    s[jj] = (kb + j <= r) ? dot : -INFINITY;
                    cmax = fmaxf(cmax, s[jj]);
                }
                const float mnew = fmaxf(m, cmax);
                const float corr = __expf(m - mnew);
                l *= corr;
                #pragma unroll
                for (int d = 0; d < Dv; d++) acc[d] *= corr;
                #pragma unroll
                for (int jj = 0; jj < 16; jj++) {
                    const int j = j0 + jj;
                    const float p = (s[jj] == -INFINITY) ? 0.f : __expf(s[jj] - mnew);
                    l += p;
                    #pragma unroll
                    for (int d = 0; d < Dv; d += 4) {
                        float4 vv = *(const float4*)&Vs[j][d];
                        acc[d]     = fmaf(p, vv.x, acc[d]);
                        acc[d + 1] = fmaf(p, vv.y, acc[d + 1]);
                        acc[d + 2] = fmaf(p, vv.z, acc[d + 2]);
                        acc[d + 3] = fmaf(p, vv.w, acc[d + 3]);
                    }
                }
                m = mnew;
            }
        }
        __syncthreads();
    }

    const float inv_l = 1.f / l;
    const size_t off = ((size_t)b * Tv + r) * Cv + h * Dv;
    #pragma unroll
    for (int d = 0; d < Dv; d += 4) {
        __nv_bfloat162 h01, h23, l01, l23;
        float f;
        __nv_bfloat16 hh;
        f = acc[d + 0] * inv_l; hh = __float2bfloat16(f); h01.x = hh; l01.x = __float2bfloat16(f - __bfloat162float(hh));
        f = acc[d + 1] * inv_l; hh = __float2bfloat16(f); h01.y = hh; l01.y = __float2bfloat16(f - __bfloat162float(hh));
        f = acc[d + 2] * inv_l; hh = __float2bfloat16(f); h23.x = hh; l23.x = __float2bfloat16(f - __bfloat162float(hh));
        f = acc[d + 3] * inv_l; hh = __float2bfloat16(f); h23.y = hh; l23.y = __float2bfloat16(f - __bfloat162float(hh));
        *(__nv_bfloat162*)(yhi + off + d)     = h01;
        *(__nv_bfloat162*)(yhi + off + d + 2) = h23;
        *(__nv_bfloat162*)(ylo + off + d)     = l01;
        *(__nv_bfloat162*)(ylo + off + d + 2) = l23;
    }
}

// ---------------------------------------------------------------------------
extern "C" void kernel_launch(void* const* d_in, const int* in_sizes, int n_in,
                              void* d_out, int out_size) {
    const float* x      = (const float*)d_in[0];
    const float* w_attn = (const float*)d_in[1];
    const float* b_attn = (const float*)d_in[2];
    const float* w_proj = (const float*)d_in[3];
    const float* b_proj = (const float*)d_in[4];
    float* out = (float*)d_out;

    float* qkv; __nv_bfloat16 *xh, *xl, *wAh, *wAl, *wPh, *wPl, *yh, *yl;
    cudaGetSymbolAddress((void**)&qkv, g_qkv);
    cudaGetSymbolAddress((void**)&xh, g_x_hi);  cudaGetSymbolAddress((void**)&xl, g_x_lo);
    cudaGetSymbolAddress((void**)&wAh, g_wA_hi); cudaGetSymbolAddress((void**)&wAl, g_wA_lo);
    cudaGetSymbolAddress((void**)&wPh, g_wP_hi); cudaGetSymbolAddress((void**)&wPl, g_wP_lo);
    cudaGetSymbolAddress((void**)&yh, g_y_hi);  cudaGetSymbolAddress((void**)&yl, g_y_lo);

    // prepare bf16-split operands
    const int nx = Mv * Cv;
    split_kernel<<<(nx / 4 + 255) / 256, 256>>>(x, xh, xl, nx);
    transpose_split<<<dim3(C3v / 32, Cv / 32), dim3(32, 8)>>>(w_attn, wAh, wAl, Cv, C3v);
    transpose_split<<<dim3(Cv / 32, Cv / 32), dim3(32, 8)>>>(w_proj, wPh, wPl, Cv, Cv);

    // 1) qkv = x @ w_attn + b_attn  [8192 x 2304]  (tensor cores)
    gemm_mma<<<dim3(C3v / 128, Mv / 128), 256>>>(xh, xl, wAh, wAl, b_attn, qkv, C3v, Cv);
    // 2) causal flash attention -> y (bf16 hi/lo)
    attn_kernel<<<dim3(Tv / 128, Hv, Bv), 128>>>(qkv, yh, yl);
    // 3) out = y @ w_proj + b_proj  [8192 x 768]  (tensor cores)
    gemm_mma<<<dim3(Cv / 128, Mv / 128), 256>>>(yh, yl, wPh, wPl, b_proj, out, Cv, Cv);
}

// round 4
// speedup vs baseline: 2.7398x; 2.7398x over previous
#include <cuda_runtime.h>
#include <cuda_bf16.h>
#include <math.h>
#include <stdint.h>

// Problem constants: B=4, T=2048, C=768, H=12, D=64
#define Bv 4
#define Tv 2048
#define Cv 768
#define Hv 12
#define Dv 64
#define C3v (3 * Cv)     // 2304
#define Mv (Bv * Tv)     // 8192

// ---------------- device scratch (no allocation allowed) -------------------
__device__ float g_qkv[(size_t)Mv * C3v];                      // [B*T, 3C] fp32
__device__ __nv_bfloat16 g_x_hi[(size_t)Mv * Cv];
__device__ __nv_bfloat16 g_x_lo[(size_t)Mv * Cv];
__device__ __nv_bfloat16 g_wA_hi[(size_t)C3v * Cv];            // transposed [3C, C]
__device__ __nv_bfloat16 g_wA_lo[(size_t)C3v * Cv];
__device__ __nv_bfloat16 g_wP_hi[(size_t)Cv * Cv];             // transposed [C, C]
__device__ __nv_bfloat16 g_wP_lo[(size_t)Cv * Cv];
__device__ __nv_bfloat16 g_y_hi[(size_t)Mv * Cv];
__device__ __nv_bfloat16 g_y_lo[(size_t)Mv * Cv];

// ---------------------------------------------------------------------------
__device__ __forceinline__ void mma16816(float* c, const uint32_t* a,
                                         uint32_t b0, uint32_t b1) {
    asm volatile(
        "mma.sync.aligned.m16n8k16.row.col.f32.bf16.bf16.f32 "
        "{%0,%1,%2,%3}, {%4,%5,%6,%7}, {%8,%9}, {%0,%1,%2,%3};"
        : "+f"(c[0]), "+f"(c[1]), "+f"(c[2]), "+f"(c[3])
        : "r"(a[0]), "r"(a[1]), "r"(a[2]), "r"(a[3]), "r"(b0), "r"(b1));
}

__device__ __forceinline__ uint32_t pack_bf(float a, float b) {
    __nv_bfloat162 t;
    t.x = __float2bfloat16(a);
    t.y = __float2bfloat16(b);
    return *(uint32_t*)&t;
}
// split pair into hi pack + residual-lo pack
__device__ __forceinline__ void split_pack(float a, float b, uint32_t& hi, uint32_t& lo) {
    float ah = __bfloat162float(__float2bfloat16(a));
    float bh = __bfloat162float(__float2bfloat16(b));
    hi = pack_bf(ah, bh);
    lo = pack_bf(a - ah, b - bh);
}

// ---------------------------------------------------------------------------
// split fp32 -> (hi, lo) bf16, elementwise
// ---------------------------------------------------------------------------
__global__ void split_kernel(const float* __restrict__ in,
                             __nv_bfloat16* __restrict__ hi,
                             __nv_bfloat16* __restrict__ lo, int n) {
    int i = (blockIdx.x * 256 + threadIdx.x) * 4;
    if (i >= n) return;
    float4 v = *(const float4*)(in + i);
    uint32_t h0, l0, h1, l1;
    split_pack(v.x, v.y, h0, l0);
    split_pack(v.z, v.w, h1, l1);
    *(uint32_t*)(hi + i)     = h0;
    *(uint32_t*)(hi + i + 2) = h1;
    *(uint32_t*)(lo + i)     = l0;
    *(uint32_t*)(lo + i + 2) = l1;
}

// ---------------------------------------------------------------------------
// transpose + split: w[K,N] fp32 -> wT[N,K] (hi, lo) bf16
// ---------------------------------------------------------------------------
__global__ void transpose_split(const float* __restrict__ w,
                                __nv_bfloat16* __restrict__ thi,
                                __nv_bfloat16* __restrict__ tlo, int K, int N) {
    __shared__ float st[32][33];
    const int n0 = blockIdx.x * 32, k0 = blockIdx.y * 32;
    const int tx = threadIdx.x, ty = threadIdx.y;          // (32, 8)
    #pragma unroll
    for (int i = 0; i < 4; i++)
        st[ty + 8 * i][tx] = w[(size_t)(k0 + ty + 8 * i) * N + n0 + tx];
    __syncthreads();
    #pragma unroll
    for (int i = 0; i < 4; i++) {
        float f = st[tx][ty + 8 * i];
        __nv_bfloat16 hh = __float2bfloat16(f);
        __nv_bfloat16 ll = __float2bfloat16(f - __bfloat162float(hh));
        size_t o = (size_t)(n0 + ty + 8 * i) * K + k0 + tx;
        thi[o] = hh;
        tlo[o] = ll;
    }
}

// ---------------------------------------------------------------------------
// Tensor-core bf16-split GEMM (unchanged from R3 — passed, 365us QKV)
// ---------------------------------------------------------------------------
#define GRS 40

__global__ __launch_bounds__(256)
void gemm_mma(const __nv_bfloat16* __restrict__ Ahi, const __nv_bfloat16* __restrict__ Alo,
              const __nv_bfloat16* __restrict__ Bhi, const __nv_bfloat16* __restrict__ Blo,
              const float* __restrict__ bias, float* __restrict__ Cmat,
              int N, int K) {
    __shared__ __nv_bfloat16 As[2][128][GRS];
    __shared__ __nv_bfloat16 Bs[2][128][GRS];

    const int tid = threadIdx.x;
    const int wid = tid >> 5, lane = tid & 31;
    const int g = lane >> 2, tig = lane & 3;
    const int bx = blockIdx.x, by = blockIdx.y;
    const int wm = (wid & 3) * 32;
    const int wn = (wid >> 2) * 64;

    const int lrow = tid >> 2;
    const int lc8  = (tid & 3) * 8;

    float acc[2][8][4];
    #pragma unroll
    for (int mt = 0; mt < 2; mt++)
        #pragma unroll
        for (int nt = 0; nt < 8; nt++)
            #pragma unroll
            for (int j = 0; j < 4; j++) acc[mt][nt][j] = 0.f;

    const int nCh = K >> 5;
    for (int c = 0; c < nCh; c++) {
        const int k0 = c << 5;
        #pragma unroll
        for (int i = 0; i < 2; i++) {
            const int r = lrow + i * 64;
            const size_t ga = (size_t)(by * 128 + r) * K + k0 + lc8;
            const size_t gb = (size_t)(bx * 128 + r) * K + k0 + lc8;
            *(uint4*)&As[0][r][lc8] = *(const uint4*)(Ahi + ga);
            *(uint4*)&As[1][r][lc8] = *(const uint4*)(Alo + ga);
            *(uint4*)&Bs[0][r][lc8] = *(const uint4*)(Bhi + gb);
            *(uint4*)&Bs[1][r][lc8] = *(const uint4*)(Blo + gb);
        }
        __syncthreads();

        #pragma unroll
        for (int pass = 0; pass < 3; pass++) {
            const int pa = (pass == 2) ? 1 : 0;
            const int pb = (pass == 1) ? 1 : 0;
            #pragma unroll
            for (int ks = 0; ks < 2; ks++) {
                const int kc = ks * 16 + tig * 2;
                uint32_t afr[2][4];
                #pragma unroll
                for (int mt = 0; mt < 2; mt++) {
                    const int r0 = wm + mt * 16 + g;
                    afr[mt][0] = *(const uint32_t*)&As[pa][r0][kc];
                    afr[mt][1] = *(const uint32_t*)&As[pa][r0 + 8][kc];
                    afr[mt][2] = *(const uint32_t*)&As[pa][r0][kc + 8];
                    afr[mt][3] = *(const uint32_t*)&As[pa][r0 + 8][kc + 8];
                }
                #pragma unroll
                for (int nt = 0; nt < 8; nt++) {
                    const int n0 = wn + nt * 8 + g;
                    const uint32_t b0 = *(const uint32_t*)&Bs[pb][n0][kc];
                    const uint32_t b1 = *(const uint32_t*)&Bs[pb][n0][kc + 8];
                    mma16816(acc[0][nt], afr[0], b0, b1);
                    mma16816(acc[1][nt], afr[1], b0, b1);
                }
            }
        }
        __syncthreads();
    }

    #pragma unroll
    for (int mt = 0; mt < 2; mt++) {
        #pragma unroll
        for (int nt = 0; nt < 8; nt++) {
            const int rg = by * 128 + wm + mt * 16 + g;
            const int cg = bx * 128 + wn + nt * 8 + tig * 2;
            const float bs0 = __ldg(bias + cg), bs1 = __ldg(bias + cg + 1);
            float2 v0, v1;
            v0.x = acc[mt][nt][0] + bs0;
            v0.y = acc[mt][nt][1] + bs1;
            v1.x = acc[mt][nt][2] + bs0;
            v1.y = acc[mt][nt][3] + bs1;
            *(float2*)(Cmat + (size_t)rg * N + cg)       = v0;
            *(float2*)(Cmat + (size_t)(rg + 8) * N + cg) = v1;
        }
    }
}

// ---------------------------------------------------------------------------
// Tensor-core causal flash attention.
// Block: 256 thr (8 warps), 128 q rows; warp = 16 rows x full D=64.
// S = Q K^T via 3-pass bf16 split (Q preloaded in regs), online softmax,
// P V via 3-pass bf16 split (V transposed in smem). Emits y as bf16 hi/lo.
// ---------------------------------------------------------------------------
#define AKS 72               // K/V^T smem row stride (bf16)
#define A_OFF_KSH 0
#define A_OFF_KSL 9216
#define A_OFF_VTH 18432
#define A_OFF_VTL 27648
#define A_OFF_VST 36864      // fp32 staging 64x68
#define A_SMEM    (36864 + 64 * 68 * 4)   // 54272

__global__ __launch_bounds__(256)
void attn_mma(const float* __restrict__ qkv,
              __nv_bfloat16* __restrict__ yhi, __nv_bfloat16* __restrict__ ylo) {
    extern __shared__ char sm[];
    __nv_bfloat16 (*Ksh)[AKS] = (__nv_bfloat16(*)[AKS])(sm + A_OFF_KSH);
    __nv_bfloat16 (*Ksl)[AKS] = (__nv_bfloat16(*)[AKS])(sm + A_OFF_KSL);
    __nv_bfloat16 (*Vth)[AKS] = (__nv_bfloat16(*)[AKS])(sm + A_OFF_VTH);
    __nv_bfloat16 (*Vtl)[AKS] = (__nv_bfloat16(*)[AKS])(sm + A_OFF_VTL);
    float (*Vst)[68]          = (float(*)[68])(sm + A_OFF_VST);

    const int qt = (gridDim.x - 1) - blockIdx.x;   // heavy blocks first
    const int h  = blockIdx.y;
    const int b  = blockIdx.z;
    const int tid = threadIdx.x;
    const int wid = tid >> 5, lane = tid & 31;
    const int g = lane >> 2, tig = lane & 3;

    const int qr0 = qt * 128;
    const int row0 = qr0 + wid * 16 + g;           // thread's first q row
    const float* base = qkv + (size_t)b * Tv * C3v;

    // ---- load Q fragments (scaled by 1/sqrt(D)), hi/lo split --------------
    uint32_t qh[4][4], ql[4][4];
    {
        const float sc = 0.125f;
        #pragma unroll
        for (int ks = 0; ks < 4; ks++) {
            const int kc = ks * 16 + tig * 2;
            #pragma unroll
            for (int j = 0; j < 4; j++) {
                const int rr = (j & 1) ? row0 + 8 : row0;
                const int cc = kc + ((j >> 1) ? 8 : 0);
                float2 v = *(const float2*)(base + (size_t)rr * C3v + h * Dv + cc);
                split_pack(v.x * sc, v.y * sc, qh[ks][j], ql[ks][j]);
            }
        }
    }

    float acc_o[8][4];
    #pragma unroll
    for (int nt = 0; nt < 8; nt++)
        #pragma unroll
        for (int j = 0; j < 4; j++) acc_o[nt][j] = 0.f;
    float m0 = -INFINITY, m1 = -INFINITY, l0 = 0.f, l1 = 0.f;

    const int nkv = (qr0 >> 6) + 2;                // kv blocks of 64
    for (int kvb = 0; kvb < nkv; kvb++) {
        const int kv0 = kvb * 64;
        // ---- load K (hi/lo, direct) + V (fp32 staging) --------------------
        #pragma unroll
        for (int i = 0; i < 4; i++) {
            const int u = tid + i * 256;
            const int r = u >> 4, c4 = (u & 15) * 4;
            const float* rowp = base + (size_t)(kv0 + r) * C3v + h * Dv + c4;
            float4 kk = *(const float4*)(rowp + Cv);
            uint32_t h0, lo0, h1, lo1;
            split_pack(kk.x, kk.y, h0, lo0);
            split_pack(kk.z, kk.w, h1, lo1);
            *(uint32_t*)&Ksh[r][c4]     = h0;
            *(uint32_t*)&Ksh[r][c4 + 2] = h1;
            *(uint32_t*)&Ksl[r][c4]     = lo0;
            *(uint32_t*)&Ksl[r][c4 + 2] = lo1;
            *(float4*)&Vst[r][c4] = *(const float4*)(rowp + 2 * Cv);
        }
        __syncthreads();
        // ---- transpose V into VsT hi/lo -----------------------------------
        {
            const int d = tid >> 2;
            const int kq = (tid & 3) * 16;
            #pragma unroll
            for (int i = 0; i < 16; i++) {
                float f = Vst[kq + i][d];
                __nv_bfloat16 hh = __float2bfloat16(f);
                Vth[d][kq + i] = hh;
                Vtl[d][kq + i] = __float2bfloat16(f - __bfloat162float(hh));
            }
        }
        __syncthreads();

        // ---- compute (skip fully-masked warps) ----------------------------
        if (kv0 <= qr0 + wid * 16 + 15) {
            float s_[8][4];
            #pragma unroll
            for (int nt = 0; nt < 8; nt++)
                #pragma unroll
                for (int j = 0; j < 4; j++) s_[nt][j] = 0.f;

            #pragma unroll
            for (int pass = 0; pass < 3; pass++) {
                #pragma unroll
                for (int ks = 0; ks < 4; ks++) {
                    const uint32_t* A = (pass == 2) ? ql[ks] : qh[ks];
                    const __nv_bfloat16 (*Bsrc)[AKS] = (pass == 1) ? Ksl : Ksh;
                    const int kc = ks * 16 + tig * 2;
                    #pragma unroll
                    for (int nt = 0; nt < 8; nt++) {
                        const int n0 = nt * 8 + g;
                        const uint32_t b0 = *(const uint32_t*)&Bsrc[n0][kc];
                        const uint32_t b1 = *(const uint32_t*)&Bsrc[n0][kc + 8];
                        mma16816(s_[nt], A, b0, b1);
                    }
                }
            }

            // mask + row max
            float rmax0 = -INFINITY, rmax1 = -INFINITY;
            #pragma unroll
            for (int nt = 0; nt < 8; nt++) {
                const int colb = kv0 + nt * 8 + tig * 2;
                #pragma unroll
                for (int j = 0; j < 2; j++) {
                    if (colb + j > row0)     s_[nt][j]     = -INFINITY;
                    if (colb + j > row0 + 8) s_[nt][2 + j] = -INFINITY;
                    rmax0 = fmaxf(rmax0, s_[nt][j]);
                    rmax1 = fmaxf(rmax1, s_[nt][2 + j]);
                }
            }
            rmax0 = fmaxf(rmax0, __shfl_xor_sync(0xffffffff, rmax0, 1));
            rmax0 = fmaxf(rmax0, __shfl_xor_sync(0xffffffff, rmax0, 2));
            rmax1 = fmaxf(rmax1, __shfl_xor_sync(0xffffffff, rmax1, 1));
            rmax1 = fmaxf(rmax1, __shfl_xor_sync(0xffffffff, rmax1, 2));

            const float mn0 = fmaxf(m0, rmax0);
            const float mn1 = fmaxf(m1, rmax1);
            const float cr0 = __expf(m0 - mn0);
            const float cr1 = __expf(m1 - mn1);
            l0 *= cr0; l1 *= cr1;
            #pragma unroll
            for (int nt = 0; nt < 8; nt++) {
                acc_o[nt][0] *= cr0; acc_o[nt][1] *= cr0;
                acc_o[nt][2] *= cr1; acc_o[nt][3] *= cr1;
            }
            m0 = mn0; m1 = mn1;

            // p = exp(s - m), split hi/lo into A fragments
            uint32_t ph[4][4], pl[4][4];
            float rs0 = 0.f, rs1 = 0.f;
            #pragma unroll
            for (int kt = 0; kt < 4; kt++) {
                float p00, p01, p10, p11;
                // ntile 2*kt  (a0: row g cols, a1: row g+8 cols)
                p00 = __expf(s_[2 * kt][0] - mn0);
                p01 = __expf(s_[2 * kt][1] - mn0);
                p10 = __expf(s_[2 * kt][2] - mn1);
                p11 = __expf(s_[2 * kt][3] - mn1);
                rs0 += p00 + p01; rs1 += p10 + p11;
                split_pack(p00, p01, ph[kt][0], pl[kt][0]);
                split_pack(p10, p11, ph[kt][1], pl[kt][1]);
                // ntile 2*kt+1 (a2, a3)
                p00 = __expf(s_[2 * kt + 1][0] - mn0);
                p01 = __expf(s_[2 * kt + 1][1] - mn0);
                p10 = __expf(s_[2 * kt + 1][2] - mn1);
                p11 = __expf(s_[2 * kt + 1][3] - mn1);
                rs0 += p00 + p01; rs1 += p10 + p11;
                split_pack(p00, p01, ph[kt][2], pl[kt][2]);
                split_pack(p10, p11, ph[kt][3], pl[kt][3]);
            }
            rs0 += __shfl_xor_sync(0xffffffff, rs0, 1);
            rs0 += __shfl_xor_sync(0xffffffff, rs0, 2);
            rs1 += __shfl_xor_sync(0xffffffff, rs1, 1);
            rs1 += __shfl_xor_sync(0xffffffff, rs1, 2);
            l0 += rs0; l1 += rs1;

            // O += P V (3-pass)
            #pragma unroll
            for (int pass = 0; pass < 3; pass++) {
                const __nv_bfloat16 (*Bsrc)[AKS] = (pass == 1) ? Vtl : Vth;
                #pragma unroll
                for (int kt = 0; kt < 4; kt++) {
                    const uint32_t* A = (pass == 2) ? pl[kt] : ph[kt];
                    const int kc = kt * 16 + tig * 2;
                    #pragma unroll
                    for (int nt = 0; nt < 8; nt++) {
                        const int n0 = nt * 8 + g;
                        const uint32_t b0 = *(const uint32_t*)&Bsrc[n0][kc];
                        const uint32_t b1 = *(const uint32_t*)&Bsrc[n0][kc + 8];
                        mma16816(acc_o[nt], A, b0, b1);
                    }
                }
            }
        }
        __syncthreads();
    }

    // ---- epilogue: y = O / l, emit bf16 hi/lo -----------------------------
    const float i0 = 1.f / l0, i1 = 1.f / l1;
    #pragma unroll
    for (int nt = 0; nt < 8; nt++) {
        const int d = nt * 8 + tig * 2;
        const size_t o0 = ((size_t)b * Tv + row0) * Cv + h * Dv + d;
        const size_t o1 = o0 + (size_t)8 * Cv;
        uint32_t hh, lo;
        split_pack(acc_o[nt][0] * i0, acc_o[nt][1] * i0, hh, lo);
        *(uint32_t*)(yhi + o0) = hh;
        *(uint32_t*)(ylo + o0) = lo;
        split_pack(acc_o[nt][2] * i1, acc_o[nt][3] * i1, hh, lo);
        *(uint32_t*)(yhi + o1) = hh;
        *(uint32_t*)(ylo + o1) = lo;
    }
}

// ---------------------------------------------------------------------------
extern "C" void kernel_launch(void* const* d_in, const int* in_sizes, int n_in,
                              void* d_out, int out_size) {
    const float* x      = (const float*)d_in[0];
    const float* w_attn = (const float*)d_in[1];
    const float* b_attn = (const float*)d_in[2];
    const float* w_proj = (const float*)d_in[3];
    const float* b_proj = (const float*)d_in[4];
    float* out = (float*)d_out;

    float* qkv; __nv_bfloat16 *xh, *xl, *wAh, *wAl, *wPh, *wPl, *yh, *yl;
    cudaGetSymbolAddress((void**)&qkv, g_qkv);
    cudaGetSymbolAddress((void**)&xh, g_x_hi);  cudaGetSymbolAddress((void**)&xl, g_x_lo);
    cudaGetSymbolAddress((void**)&wAh, g_wA_hi); cudaGetSymbolAddress((void**)&wAl, g_wA_lo);
    cudaGetSymbolAddress((void**)&wPh, g_wP_hi); cudaGetSymbolAddress((void**)&wPl, g_wP_lo);
    cudaGetSymbolAddress((void**)&yh, g_y_hi);  cudaGetSymbolAddress((void**)&yl, g_y_lo);

    cudaFuncSetAttribute(attn_mma, cudaFuncAttributeMaxDynamicSharedMemorySize, A_SMEM);

    // prepare bf16-split operands
    const int nx = Mv * Cv;
    split_kernel<<<(nx / 4 + 255) / 256, 256>>>(x, xh, xl, nx);
    transpose_split<<<dim3(C3v / 32, Cv / 32), dim3(32, 8)>>>(w_attn, wAh, wAl, Cv, C3v);
    transpose_split<<<dim3(Cv / 32, Cv / 32), dim3(32, 8)>>>(w_proj, wPh, wPl, Cv, Cv);

    // 1) qkv = x @ w_attn + b_attn  [8192 x 2304]  (tensor cores)
    gemm_mma<<<dim3(C3v / 128, Mv / 128), 256>>>(xh, xl, wAh, wAl, b_attn, qkv, C3v, Cv);
    // 2) causal flash attention -> y (bf16 hi/lo)  (tensor cores)
    attn_mma<<<dim3(Tv / 128, Hv, Bv), 256, A_SMEM>>>(qkv, yh, yl);
    // 3) out = y @ w_proj + b_proj  [8192 x 768]  (tensor cores)
    gemm_mma<<<dim3(Cv / 128, Mv / 128), 256>>>(yh, yl, wPh, wPl, b_proj, out, Cv, Cv);
}

// round 5
// speedup vs baseline: 3.0531x; 1.1143x over previous
#include <cuda_runtime.h>
#include <cuda_bf16.h>
#include <math.h>
#include <stdint.h>

// Problem constants: B=4, T=2048, C=768, H=12, D=64
#define Bv 4
#define Tv 2048
#define Cv 768
#define Hv 12
#define Dv 64
#define C3v (3 * Cv)     // 2304
#define Mv (Bv * Tv)     // 8192

// ---------------- device scratch (no allocation allowed) -------------------
__device__ float g_qkv[(size_t)Mv * C3v];                      // [B*T, 3C] fp32
__device__ __nv_bfloat16 g_x_hi[(size_t)Mv * Cv];
__device__ __nv_bfloat16 g_x_lo[(size_t)Mv * Cv];
__device__ __nv_bfloat16 g_wA_hi[(size_t)C3v * Cv];            // transposed [3C, C]
__device__ __nv_bfloat16 g_wA_lo[(size_t)C3v * Cv];
__device__ __nv_bfloat16 g_wP_hi[(size_t)Cv * Cv];             // transposed [C, C]
__device__ __nv_bfloat16 g_wP_lo[(size_t)Cv * Cv];
__device__ __nv_bfloat16 g_y_hi[(size_t)Mv * Cv];
__device__ __nv_bfloat16 g_y_lo[(size_t)Mv * Cv];

// ---------------------------------------------------------------------------
__device__ __forceinline__ void mma16816(float* c, const uint32_t* a,
                                         uint32_t b0, uint32_t b1) {
    asm volatile(
        "mma.sync.aligned.m16n8k16.row.col.f32.bf16.bf16.f32 "
        "{%0,%1,%2,%3}, {%4,%5,%6,%7}, {%8,%9}, {%0,%1,%2,%3};"
        : "+f"(c[0]), "+f"(c[1]), "+f"(c[2]), "+f"(c[3])
        : "r"(a[0]), "r"(a[1]), "r"(a[2]), "r"(a[3]), "r"(b0), "r"(b1));
}

__device__ __forceinline__ uint32_t smem_u32(const void* p) {
    uint32_t a;
    asm("{ .reg .u64 t; cvta.to.shared.u64 t, %1; cvt.u32.u64 %0, t; }" : "=r"(a) : "l"(p));
    return a;
}
#define CP16(dst, src) \
    asm volatile("cp.async.cg.shared.global [%0], [%1], 16;" :: "r"(dst), "l"(src))
#define CP_COMMIT() asm volatile("cp.async.commit_group;" ::: "memory")
#define CP_WAIT1()  asm volatile("cp.async.wait_group 1;" ::: "memory")
#define CP_WAIT0()  asm volatile("cp.async.wait_group 0;" ::: "memory")

__device__ __forceinline__ uint32_t pack_bf(float a, float b) {
    __nv_bfloat162 t;
    t.x = __float2bfloat16(a);
    t.y = __float2bfloat16(b);
    return *(uint32_t*)&t;
}
__device__ __forceinline__ void split_pack(float a, float b, uint32_t& hi, uint32_t& lo) {
    float ah = __bfloat162float(__float2bfloat16(a));
    float bh = __bfloat162float(__float2bfloat16(b));
    hi = pack_bf(ah, bh);
    lo = pack_bf(a - ah, b - bh);
}

// ---------------------------------------------------------------------------
__global__ void split_kernel(const float* __restrict__ in,
                             __nv_bfloat16* __restrict__ hi,
                             __nv_bfloat16* __restrict__ lo, int n) {
    int i = (blockIdx.x * 256 + threadIdx.x) * 4;
    if (i >= n) return;
    float4 v = *(const float4*)(in + i);
    uint32_t h0, l0, h1, l1;
    split_pack(v.x, v.y, h0, l0);
    split_pack(v.z, v.w, h1, l1);
    *(uint32_t*)(hi + i)     = h0;
    *(uint32_t*)(hi + i + 2) = h1;
    *(uint32_t*)(lo + i)     = l0;
    *(uint32_t*)(lo + i + 2) = l1;
}

__global__ void transpose_split(const float* __restrict__ w,
                                __nv_bfloat16* __restrict__ thi,
                                __nv_bfloat16* __restrict__ tlo, int K, int N) {
    __shared__ float st[32][33];
    const int n0 = blockIdx.x * 32, k0 = blockIdx.y * 32;
    const int tx = threadIdx.x, ty = threadIdx.y;          // (32, 8)
    #pragma unroll
    for (int i = 0; i < 4; i++)
        st[ty + 8 * i][tx] = w[(size_t)(k0 + ty + 8 * i) * N + n0 + tx];
    __syncthreads();
    #pragma unroll
    for (int i = 0; i < 4; i++) {
        float f = st[tx][ty + 8 * i];
        __nv_bfloat16 hh = __float2bfloat16(f);
        __nv_bfloat16 ll = __float2bfloat16(f - __bfloat162float(hh));
        size_t o = (size_t)(n0 + ty + 8 * i) * K + k0 + tx;
        thi[o] = hh;
        tlo[o] = ll;
    }
}

// ---------------------------------------------------------------------------
// Tensor-core bf16-split GEMM, cp.async double-buffered.
//   C[M,N] = (Ahi+Alo)[M,K] @ (Bhi+Blo)[N,K]^T + bias
// 128x128 tile, BK=32, 8 warps (4Mx2N). smem row stride 40 bf16 (80B, 16B-mult).
// Layout (dynamic smem): tile(s, part) = 10240B each.
//   A tiles: [stage][hi/lo] at (s*2+p)*10240 ; B tiles at 40960 + same.
// ---------------------------------------------------------------------------
#define GRS 40
#define GT_BYTES 10240                 // 128 * 40 * 2
#define GB_OFF   (4 * GT_BYTES)        // B region offset = 40960
#define G_SMEM   (8 * GT_BYTES)        // 81920

__global__ __launch_bounds__(256)
void gemm_mma(const __nv_bfloat16* __restrict__ Ahi, const __nv_bfloat16* __restrict__ Alo,
              const __nv_bfloat16* __restrict__ Bhi, const __nv_bfloat16* __restrict__ Blo,
              const float* __restrict__ bias, float* __restrict__ Cmat,
              int N, int K) {
    extern __shared__ __align__(16) char gsm[];
    const uint32_t sb = smem_u32(gsm);

    const int tid = threadIdx.x;
    const int wid = tid >> 5, lane = tid & 31;
    const int g = lane >> 2, tig = lane & 3;
    const int bx = blockIdx.x, by = blockIdx.y;
    const int wm = (wid & 3) * 32;
    const int wn = (wid >> 2) * 64;

    const int lrow = tid >> 2;                  // 0..63
    const int lc8  = (tid & 3) * 8;             // 0,8,16,24

    float acc[2][8][4];
    #pragma unroll
    for (int mt = 0; mt < 2; mt++)
        #pragma unroll
        for (int nt = 0; nt < 8; nt++)
            #pragma unroll
            for (int j = 0; j < 4; j++) acc[mt][nt][j] = 0.f;

    const int nCh = K >> 5;

    // async-load one K-chunk into stage s
    auto load_chunk = [&](int c, int s) {
        const int k0 = c << 5;
        #pragma unroll
        for (int i = 0; i < 2; i++) {
            const int r = lrow + i * 64;
            const size_t ga = (size_t)(by * 128 + r) * K + k0 + lc8;
            const size_t gb = (size_t)(bx * 128 + r) * K + k0 + lc8;
            const uint32_t ro = (uint32_t)(r * (GRS * 2) + lc8 * 2);
            CP16(sb + (s * 2 + 0) * GT_BYTES + ro,          Ahi + ga);
            CP16(sb + (s * 2 + 1) * GT_BYTES + ro,          Alo + ga);
            CP16(sb + GB_OFF + (s * 2 + 0) * GT_BYTES + ro, Bhi + gb);
            CP16(sb + GB_OFF + (s * 2 + 1) * GT_BYTES + ro, Blo + gb);
        }
    };

    load_chunk(0, 0);
    CP_COMMIT();

    for (int c = 0; c < nCh; c++) {
        const int s = c & 1;
        if (c + 1 < nCh) {
            load_chunk(c + 1, s ^ 1);
            CP_COMMIT();
            CP_WAIT1();
        } else {
            CP_WAIT0();
        }
        __syncthreads();

        #pragma unroll
        for (int pass = 0; pass < 3; pass++) {
            const int pa = (pass == 2) ? 1 : 0;
            const int pb = (pass == 1) ? 1 : 0;
            const __nv_bfloat16 (*Asp)[GRS] =
                (const __nv_bfloat16(*)[GRS])(gsm + (s * 2 + pa) * GT_BYTES);
            const __nv_bfloat16 (*Bsp)[GRS] =
                (const __nv_bfloat16(*)[GRS])(gsm + GB_OFF + (s * 2 + pb) * GT_BYTES);
            #pragma unroll
            for (int ks = 0; ks < 2; ks++) {
                const int kc = ks * 16 + tig * 2;
                uint32_t afr[2][4];
                #pragma unroll
                for (int mt = 0; mt < 2; mt++) {
                    const int r0 = wm + mt * 16 + g;
                    afr[mt][0] = *(const uint32_t*)&Asp[r0][kc];
                    afr[mt][1] = *(const uint32_t*)&Asp[r0 + 8][kc];
                    afr[mt][2] = *(const uint32_t*)&Asp[r0][kc + 8];
                    afr[mt][3] = *(const uint32_t*)&Asp[r0 + 8][kc + 8];
                }
                #pragma unroll
                for (int nt = 0; nt < 8; nt++) {
                    const int n0 = wn + nt * 8 + g;
                    const uint32_t b0 = *(const uint32_t*)&Bsp[n0][kc];
                    const uint32_t b1 = *(const uint32_t*)&Bsp[n0][kc + 8];
                    mma16816(acc[0][nt], afr[0], b0, b1);
                    mma16816(acc[1][nt], afr[1], b0, b1);
                }
            }
        }
        __syncthreads();
    }

    #pragma unroll
    for (int mt = 0; mt < 2; mt++) {
        #pragma unroll
        for (int nt = 0; nt < 8; nt++) {
            const int rg = by * 128 + wm + mt * 16 + g;
            const int cg = bx * 128 + wn + nt * 8 + tig * 2;
            const float bs0 = __ldg(bias + cg), bs1 = __ldg(bias + cg + 1);
            float2 v0, v1;
            v0.x = acc[mt][nt][0] + bs0;
            v0.y = acc[mt][nt][1] + bs1;
            v1.x = acc[mt][nt][2] + bs0;
            v1.y = acc[mt][nt][3] + bs1;
            *(float2*)(Cmat + (size_t)rg * N + cg)       = v0;
            *(float2*)(Cmat + (size_t)(rg + 8) * N + cg) = v1;
        }
    }
}

// ---------------------------------------------------------------------------
// Tensor-core causal flash attention (unchanged from R4 — ~360us).
// ---------------------------------------------------------------------------
#define AKS 72               // K/V^T smem row stride (bf16)
#define A_OFF_KSH 0
#define A_OFF_KSL 9216
#define A_OFF_VTH 18432
#define A_OFF_VTL 27648
#define A_OFF_VST 36864      // fp32 staging 64x68
#define A_SMEM    (36864 + 64 * 68 * 4)   // 54272

__global__ __launch_bounds__(256)
void attn_mma(const float* __restrict__ qkv,
              __nv_bfloat16* __restrict__ yhi, __nv_bfloat16* __restrict__ ylo) {
    extern __shared__ char sm[];
    __nv_bfloat16 (*Ksh)[AKS] = (__nv_bfloat16(*)[AKS])(sm + A_OFF_KSH);
    __nv_bfloat16 (*Ksl)[AKS] = (__nv_bfloat16(*)[AKS])(sm + A_OFF_KSL);
    __nv_bfloat16 (*Vth)[AKS] = (__nv_bfloat16(*)[AKS])(sm + A_OFF_VTH);
    __nv_bfloat16 (*Vtl)[AKS] = (__nv_bfloat16(*)[AKS])(sm + A_OFF_VTL);
    float (*Vst)[68]          = (float(*)[68])(sm + A_OFF_VST);

    const int qt = (gridDim.x - 1) - blockIdx.x;   // heavy blocks first
    const int h  = blockIdx.y;
    const int b  = blockIdx.z;
    const int tid = threadIdx.x;
    const int wid = tid >> 5, lane = tid & 31;
    const int g = lane >> 2, tig = lane & 3;

    const int qr0 = qt * 128;
    const int row0 = qr0 + wid * 16 + g;
    const float* base = qkv + (size_t)b * Tv * C3v;

    uint32_t qh[4][4], ql[4][4];
    {
        const float sc = 0.125f;
        #pragma unroll
        for (int ks = 0; ks < 4; ks++) {
            const int kc = ks * 16 + tig * 2;
            #pragma unroll
            for (int j = 0; j < 4; j++) {
                const int rr = (j & 1) ? row0 + 8 : row0;
                const int cc = kc + ((j >> 1) ? 8 : 0);
                float2 v = *(const float2*)(base + (size_t)rr * C3v + h * Dv + cc);
                split_pack(v.x * sc, v.y * sc, qh[ks][j], ql[ks][j]);
            }
        }
    }

    float acc_o[8][4];
    #pragma unroll
    for (int nt = 0; nt < 8; nt++)
        #pragma unroll
        for (int j = 0; j < 4; j++) acc_o[nt][j] = 0.f;
    float m0 = -INFINITY, m1 = -INFINITY, l0 = 0.f, l1 = 0.f;

    const int nkv = (qr0 >> 6) + 2;
    for (int kvb = 0; kvb < nkv; kvb++) {
        const int kv0 = kvb * 64;
        #pragma unroll
        for (int i = 0; i < 4; i++) {
            const int u = tid + i * 256;
            const int r = u >> 4, c4 = (u & 15) * 4;
            const float* rowp = base + (size_t)(kv0 + r) * C3v + h * Dv + c4;
            float4 kk = *(const float4*)(rowp + Cv);
            uint32_t h0, lo0, h1, lo1;
            split_pack(kk.x, kk.y, h0, lo0);
            split_pack(kk.z, kk.w, h1, lo1);
            *(uint32_t*)&Ksh[r][c4]     = h0;
            *(uint32_t*)&Ksh[r][c4 + 2] = h1;
            *(uint32_t*)&Ksl[r][c4]     = lo0;
            *(uint32_t*)&Ksl[r][c4 + 2] = lo1;
            *(float4*)&Vst[r][c4] = *(const float4*)(rowp + 2 * Cv);
        }
        __syncthreads();
        {
            const int d = tid >> 2;
            const int kq = (tid & 3) * 16;
            #pragma unroll
            for (int i = 0; i < 16; i++) {
                float f = Vst[kq + i][d];
                __nv_bfloat16 hh = __float2bfloat16(f);
                Vth[d][kq + i] = hh;
                Vtl[d][kq + i] = __float2bfloat16(f - __bfloat162float(hh));
            }
        }
        __syncthreads();

        if (kv0 <= qr0 + wid * 16 + 15) {
            float s_[8][4];
            #pragma unroll
            for (int nt = 0; nt < 8; nt++)
                #pragma unroll
                for (int j = 0; j < 4; j++) s_[nt][j] = 0.f;

            #pragma unroll
            for (int pass = 0; pass < 3; pass++) {
                #pragma unroll
                for (int ks = 0; ks < 4; ks++) {
                    const uint32_t* A = (pass == 2) ? ql[ks] : qh[ks];
                    const __nv_bfloat16 (*Bsrc)[AKS] = (pass == 1) ? Ksl : Ksh;
                    const int kc = ks * 16 + tig * 2;
                    #pragma unroll
                    for (int nt = 0; nt < 8; nt++) {
                        const int n0 = nt * 8 + g;
                        const uint32_t b0 = *(const uint32_t*)&Bsrc[n0][kc];
                        const uint32_t b1 = *(const uint32_t*)&Bsrc[n0][kc + 8];
                        mma16816(s_[nt], A, b0, b1);
                    }
                }
            }

            float rmax0 = -INFINITY, rmax1 = -INFINITY;
            #pragma unroll
            for (int nt = 0; nt < 8; nt++) {
                const int colb = kv0 + nt * 8 + tig * 2;
                #pragma unroll
                for (int j = 0; j < 2; j++) {
                    if (colb + j > row0)     s_[nt][j]     = -INFINITY;
                    if (colb + j > row0 + 8) s_[nt][2 + j] = -INFINITY;
                    rmax0 = fmaxf(rmax0, s_[nt][j]);
                    rmax1 = fmaxf(rmax1, s_[nt][2 + j]);
                }
            }
            rmax0 = fmaxf(rmax0, __shfl_xor_sync(0xffffffff, rmax0, 1));
            rmax0 = fmaxf(rmax0, __shfl_xor_sync(0xffffffff, rmax0, 2));
            rmax1 = fmaxf(rmax1, __shfl_xor_sync(0xffffffff, rmax1, 1));
            rmax1 = fmaxf(rmax1, __shfl_xor_sync(0xffffffff, rmax1, 2));

            const float mn0 = fmaxf(m0, rmax0);
            const float mn1 = fmaxf(m1, rmax1);
            const float cr0 = __expf(m0 - mn0);
            const float cr1 = __expf(m1 - mn1);
            l0 *= cr0; l1 *= cr1;
            #pragma unroll
            for (int nt = 0; nt < 8; nt++) {
                acc_o[nt][0] *= cr0; acc_o[nt][1] *= cr0;
                acc_o[nt][2] *= cr1; acc_o[nt][3] *= cr1;
            }
            m0 = mn0; m1 = mn1;

            uint32_t ph[4][4], pl[4][4];
            float rs0 = 0.f, rs1 = 0.f;
            #pragma unroll
            for (int kt = 0; kt < 4; kt++) {
                float p00, p01, p10, p11;
                p00 = __expf(s_[2 * kt][0] - mn0);
                p01 = __expf(s_[2 * kt][1] - mn0);
                p10 = __expf(s_[2 * kt][2] - mn1);
                p11 = __expf(s_[2 * kt][3] - mn1);
                rs0 += p00 + p01; rs1 += p10 + p11;
                split_pack(p00, p01, ph[kt][0], pl[kt][0]);
                split_pack(p10, p11, ph[kt][1], pl[kt][1]);
                p00 = __expf(s_[2 * kt + 1][0] - mn0);
                p01 = __expf(s_[2 * kt + 1][1] - mn0);
                p10 = __expf(s_[2 * kt + 1][2] - mn1);
                p11 = __expf(s_[2 * kt + 1][3] - mn1);
                rs0 += p00 + p01; rs1 += p10 + p11;
                split_pack(p00, p01, ph[kt][2], pl[kt][2]);
                split_pack(p10, p11, ph[kt][3], pl[kt][3]);
            }
            rs0 += __shfl_xor_sync(0xffffffff, rs0, 1);
            rs0 += __shfl_xor_sync(0xffffffff, rs0, 2);
            rs1 += __shfl_xor_sync(0xffffffff, rs1, 1);
            rs1 += __shfl_xor_sync(0xffffffff, rs1, 2);
            l0 += rs0; l1 += rs1;

            #pragma unroll
            for (int pass = 0; pass < 3; pass++) {
                const __nv_bfloat16 (*Bsrc)[AKS] = (pass == 1) ? Vtl : Vth;
                #pragma unroll
                for (int kt = 0; kt < 4; kt++) {
                    const uint32_t* A = (pass == 2) ? pl[kt] : ph[kt];
                    const int kc = kt * 16 + tig * 2;
                    #pragma unroll
                    for (int nt = 0; nt < 8; nt++) {
                        const int n0 = nt * 8 + g;
                        const uint32_t b0 = *(const uint32_t*)&Bsrc[n0][kc];
                        const uint32_t b1 = *(const uint32_t*)&Bsrc[n0][kc + 8];
                        mma16816(acc_o[nt], A, b0, b1);
                    }
                }
            }
        }
        __syncthreads();
    }

    const float i0 = 1.f / l0, i1 = 1.f / l1;
    #pragma unroll
    for (int nt = 0; nt < 8; nt++) {
        const int d = nt * 8 + tig * 2;
        const size_t o0 = ((size_t)b * Tv + row0) * Cv + h * Dv + d;
        const size_t o1 = o0 + (size_t)8 * Cv;
        uint32_t hh, lo;
        split_pack(acc_o[nt][0] * i0, acc_o[nt][1] * i0, hh, lo);
        *(uint32_t*)(yhi + o0) = hh;
        *(uint32_t*)(ylo + o0) = lo;
        split_pack(acc_o[nt][2] * i1, acc_o[nt][3] * i1, hh, lo);
        *(uint32_t*)(yhi + o1) = hh;
        *(uint32_t*)(ylo + o1) = lo;
    }
}

// ---------------------------------------------------------------------------
extern "C" void kernel_launch(void* const* d_in, const int* in_sizes, int n_in,
                              void* d_out, int out_size) {
    const float* x      = (const float*)d_in[0];
    const float* w_attn = (const float*)d_in[1];
    const float* b_attn = (const float*)d_in[2];
    const float* w_proj = (const float*)d_in[3];
    const float* b_proj = (const float*)d_in[4];
    float* out = (float*)d_out;

    float* qkv; __nv_bfloat16 *xh, *xl, *wAh, *wAl, *wPh, *wPl, *yh, *yl;
    cudaGetSymbolAddress((void**)&qkv, g_qkv);
    cudaGetSymbolAddress((void**)&xh, g_x_hi);  cudaGetSymbolAddress((void**)&xl, g_x_lo);
    cudaGetSymbolAddress((void**)&wAh, g_wA_hi); cudaGetSymbolAddress((void**)&wAl, g_wA_lo);
    cudaGetSymbolAddress((void**)&wPh, g_wP_hi); cudaGetSymbolAddress((void**)&wPl, g_wP_lo);
    cudaGetSymbolAddress((void**)&yh, g_y_hi);  cudaGetSymbolAddress((void**)&yl, g_y_lo);

    cudaFuncSetAttribute(gemm_mma, cudaFuncAttributeMaxDynamicSharedMemorySize, G_SMEM);
    cudaFuncSetAttribute(attn_mma, cudaFuncAttributeMaxDynamicSharedMemorySize, A_SMEM);

    // prepare bf16-split operands
    const int nx = Mv * Cv;
    split_kernel<<<(nx / 4 + 255) / 256, 256>>>(x, xh, xl, nx);
    transpose_split<<<dim3(C3v / 32, Cv / 32), dim3(32, 8)>>>(w_attn, wAh, wAl, Cv, C3v);
    transpose_split<<<dim3(Cv / 32, Cv / 32), dim3(32, 8)>>>(w_proj, wPh, wPl, Cv, Cv);

    // 1) qkv = x @ w_attn + b_attn  [8192 x 2304]  (tensor cores, pipelined)
    gemm_mma<<<dim3(C3v / 128, Mv / 128), 256, G_SMEM>>>(xh, xl, wAh, wAl, b_attn, qkv, C3v, Cv);
    // 2) causal flash attention -> y (bf16 hi/lo)  (tensor cores)
    attn_mma<<<dim3(Tv / 128, Hv, Bv), 256, A_SMEM>>>(qkv, yh, yl);
    // 3) out = y @ w_proj + b_proj  [8192 x 768]  (tensor cores, pipelined)
    gemm_mma<<<dim3(Cv / 128, Mv / 128), 256, G_SMEM>>>(yh, yl, wPh, wPl, b_proj, out, Cv, Cv);
}